// round 12
// baseline (speedup 1.0000x reference)
#include <cuda_runtime.h>

// inputs (128, 64, 64, 32) fp32 => B=128, N=64 rows/batch, D=2048.
// loss = mean_b( || sum_n att[b,n,:] ||^2 - sum_n <att_n,att_n> ),
// att = x / max(||x||,1e-12) row-wise.
//
// Warp-autonomous design: a warp spans a full row (32 lanes x 16 f4).
// Per row: read -> sumsq (5 shuffles, NO block barrier) -> inv -> re-read
// (L1-hot) -> FMA into register-resident full-width accumulator acc[16].
// Block = 4 warps x 4 rows = 16 rows; grid 512 = 4 blocks/batch.

#define BB   128
#define NN   64
#define DD   2048
#define NF4  (DD / 4)      // 512 f4 columns
#define NT   128           // 4 warps
#define GRID (BB * 4)      // 512 blocks

__device__ float4       g_s[BB][4][NF4];   // per-(batch,quarter) col sums
__device__ float        g_diagp[GRID];
__device__ double       g_part[BB];
__device__ unsigned int g_pair[BB];        // monotonic (never reset)
__device__ unsigned int g_done;            // monotonic (never reset)

__global__ __launch_bounds__(NT, 4) void fused_loss(const float* __restrict__ x,
                                                    float* __restrict__ out) {
    __shared__ float4 sbuf[3][NF4];      // 24 KB warp-combine buffer
    __shared__ float  sdg[4];
    __shared__ float  w1[4];
    __shared__ bool   s_4th, s_last;
    __shared__ double sdd[NT];

    const int bid  = blockIdx.x;
    const int b    = bid >> 2;         // batch
    const int qb   = bid & 3;          // quarter of the batch's rows
    const int t    = threadIdx.x;
    const int warp = t >> 5;
    const int lane = t & 31;
    const float4* base4 = reinterpret_cast<const float4*>(x + (size_t)b * NN * DD);

    float4 acc[16];
    #pragma unroll
    for (int j = 0; j < 16; j++) acc[j] = make_float4(0.f, 0.f, 0.f, 0.f);
    float diag = 0.f;

    // ---------------- main loop: 4 rows per warp, barrier-free --------------
    #pragma unroll 1
    for (int r = 0; r < 4; r++) {
        const int row = qb * 16 + warp * 4 + r;
        const float4* p = base4 + (size_t)row * NF4 + lane;

        // pass 1: sum of squares (two waves of 8 independent LDG.128)
        float4 v[8];
        #pragma unroll
        for (int j = 0; j < 8; j++) v[j] = p[j * 32];
        float c0 = 0.f, c1 = 0.f, c2 = 0.f, c3 = 0.f;
        #pragma unroll
        for (int j = 0; j < 8; j += 4) {
            c0 += v[j+0].x*v[j+0].x + v[j+0].y*v[j+0].y + v[j+0].z*v[j+0].z + v[j+0].w*v[j+0].w;
            c1 += v[j+1].x*v[j+1].x + v[j+1].y*v[j+1].y + v[j+1].z*v[j+1].z + v[j+1].w*v[j+1].w;
            c2 += v[j+2].x*v[j+2].x + v[j+2].y*v[j+2].y + v[j+2].z*v[j+2].z + v[j+2].w*v[j+2].w;
            c3 += v[j+3].x*v[j+3].x + v[j+3].y*v[j+3].y + v[j+3].z*v[j+3].z + v[j+3].w*v[j+3].w;
        }
        #pragma unroll
        for (int j = 0; j < 8; j++) v[j] = p[(8 + j) * 32];
        #pragma unroll
        for (int j = 0; j < 8; j += 4) {
            c0 += v[j+0].x*v[j+0].x + v[j+0].y*v[j+0].y + v[j+0].z*v[j+0].z + v[j+0].w*v[j+0].w;
            c1 += v[j+1].x*v[j+1].x + v[j+1].y*v[j+1].y + v[j+1].z*v[j+1].z + v[j+1].w*v[j+1].w;
            c2 += v[j+2].x*v[j+2].x + v[j+2].y*v[j+2].y + v[j+2].z*v[j+2].z + v[j+2].w*v[j+2].w;
            c3 += v[j+3].x*v[j+3].x + v[j+3].y*v[j+3].y + v[j+3].z*v[j+3].z + v[j+3].w*v[j+3].w;
        }
        float ss = (c0 + c1) + (c2 + c3);
        #pragma unroll
        for (int o = 16; o; o >>= 1) ss += __shfl_xor_sync(0xffffffffu, ss, o);

        // inv = 1/max(||row||,1e-12)  (ss >= 1e-24 <=> norm >= 1e-12)
        const float inv = rsqrtf(fmaxf(ss, 1e-24f));
        if (lane == 0) diag += ss * inv * inv;

        // pass 2: re-read row (L1 hits) and accumulate inv * x
        #pragma unroll
        for (int j = 0; j < 16; j++) {
            const float4 a = p[j * 32];
            acc[j].x = fmaf(inv, a.x, acc[j].x);
            acc[j].y = fmaf(inv, a.y, acc[j].y);
            acc[j].z = fmaf(inv, a.z, acc[j].z);
            acc[j].w = fmaf(inv, a.w, acc[j].w);
        }
    }

    // ---------------- combine 4 warps -> quarter partial --------------------
    if (warp > 0) {
        #pragma unroll
        for (int j = 0; j < 16; j++) sbuf[warp - 1][lane + 32 * j] = acc[j];
    }
    if (lane == 0) sdg[warp] = diag;
    __syncthreads();
    if (warp == 0) {
        #pragma unroll
        for (int j = 0; j < 16; j++) {
            float4 a = acc[j];
            #pragma unroll
            for (int k = 0; k < 3; k++) {
                const float4 q = sbuf[k][lane + 32 * j];
                a.x += q.x; a.y += q.y; a.z += q.z; a.w += q.w;
            }
            g_s[b][qb][lane + 32 * j] = a;
        }
    }
    if (t == 0) g_diagp[bid] = sdg[0] + sdg[1] + sdg[2] + sdg[3];
    __threadfence();                 // each thread orders its own stores
    __syncthreads();

    // ---------------- 4th-arriving block of batch computes t1 ---------------
    if (t == 0) {
        unsigned int old = atomicAdd(&g_pair[b], 1u);
        s_4th = ((old & 3u) == 3u);
    }
    __syncthreads();
    if (!s_4th) return;
    __threadfence();

    float v1 = 0.f;
    #pragma unroll
    for (int j = 0; j < 4; j++) {
        const int col = t + NT * j;
        const float4 A  = g_s[b][0][col];
        const float4 Bq = g_s[b][1][col];
        const float4 C  = g_s[b][2][col];
        const float4 Dq = g_s[b][3][col];
        const float sx = (A.x + Bq.x) + (C.x + Dq.x);
        const float sy = (A.y + Bq.y) + (C.y + Dq.y);
        const float sz = (A.z + Bq.z) + (C.z + Dq.z);
        const float sw = (A.w + Bq.w) + (C.w + Dq.w);
        v1 += sx*sx + sy*sy + sz*sz + sw*sw;
    }
    #pragma unroll
    for (int o = 16; o; o >>= 1) v1 += __shfl_xor_sync(0xffffffffu, v1, o);
    if (lane == 0) w1[warp] = v1;
    __syncthreads();

    if (t == 0) {
        const float t1 = (w1[0] + w1[1]) + (w1[2] + w1[3]);
        const double t2 = (double)g_diagp[4*b] + (double)g_diagp[4*b+1]
                        + (double)g_diagp[4*b+2] + (double)g_diagp[4*b+3];
        g_part[b] = (double)t1 - t2;
        __threadfence();
        unsigned int old = atomicAdd(&g_done, 1u);
        s_last = ((old & (unsigned int)(BB - 1)) == (unsigned int)(BB - 1));
    }
    __syncthreads();
    if (!s_last) return;

    // ---------------- finisher: combine 128 per-batch doubles ---------------
    __threadfence();
    sdd[t] = g_part[t];              // NT == BB == 128
    __syncthreads();
    #pragma unroll
    for (int o = NT / 2; o; o >>= 1) {
        if (t < o) sdd[t] += sdd[t + o];
        __syncthreads();
    }
    if (t == 0) out[0] = (float)(sdd[0] / (double)BB);
}

extern "C" void kernel_launch(void* const* d_in, const int* in_sizes, int n_in,
                              void* d_out, int out_size) {
    (void)in_sizes; (void)n_in; (void)out_size;
    const float* x = (const float*)d_in[0];
    float* out = (float*)d_out;
    fused_loss<<<GRID, NT>>>(x, out);
}